// round 1
// baseline (speedup 1.0000x reference)
#include <cuda_runtime.h>
#include <cstdint>

#define NNODES 32768
// hidden = out = 64, D_IN = 4, msg dim = 7 (x:4 rows 0-3 of W1, rel:3 rows 4-6)

__device__ float g_a[NNODES * 64];   // pre-relu first-layer activations per node (b1 folded in)

__device__ __forceinline__ void atomicMaxF(float* addr, float v) {
    // standard sign-split trick; valid for non-NaN floats
    if (v >= 0.0f) atomicMax((int*)addr, __float_as_int(v));
    else           atomicMin((unsigned int*)addr, __float_as_uint(v));
}

__device__ __forceinline__ unsigned long long pack2(float lo, float hi) {
    unsigned long long r;
    asm("mov.b64 %0, {%1,%2};" : "=l"(r) : "f"(lo), "f"(hi));
    return r;
}
__device__ __forceinline__ void unpack2(unsigned long long p, float& lo, float& hi) {
    asm("mov.b64 {%0,%1}, %2;" : "=f"(lo), "=f"(hi) : "l"(p));
}
__device__ __forceinline__ void fma2(unsigned long long& acc,
                                     unsigned long long a, unsigned long long b) {
    asm("fma.rn.f32x2 %0, %1, %2, %3;" : "=l"(acc) : "l"(a), "l"(b), "l"(acc));
}
__device__ __forceinline__ unsigned long long add2(unsigned long long a, unsigned long long b) {
    unsigned long long r;
    asm("add.rn.f32x2 %0, %1, %2;" : "=l"(r) : "l"(a), "l"(b));
    return r;
}

// 64x64 second-layer GEMV for one edge: td holds (t_k, t_k) duplicated pairs, k=0..63.
// w2[k] holds (W2[k][lane], W2[k][lane+32]). Two independent accumulator chains.
__device__ __forceinline__ void gemm64(const unsigned long long* __restrict__ td,
                                       const unsigned long long* __restrict__ w2,
                                       unsigned long long b2p,
                                       float& h0, float& h1) {
    unsigned long long acc0 = b2p;
    unsigned long long acc1 = pack2(0.0f, 0.0f);
#pragma unroll
    for (int k = 0; k < 64; k += 2) {
        ulonglong2 tp = *reinterpret_cast<const ulonglong2*>(td + k);  // (t_k,t_k),(t_k+1,t_k+1)
        fma2(acc0, tp.x, w2[k]);
        fma2(acc1, tp.y, w2[k + 1]);
    }
    acc0 = add2(acc0, acc1);
    unpack2(acc0, h0, h1);
}

// ---------------------------------------------------------------------------
// Kernel 1: per-node. Computes g_a[n] = x[n]@W1[0:4] + b1 (pre-relu) and
// initializes out[n] with the self-loop contribution relu(g_a[n])@W2 + b2.
// One warp per node (grid-stride over nodes).
// ---------------------------------------------------------------------------
__global__ void __launch_bounds__(128) node_kernel(
    const float* __restrict__ x,
    const float* __restrict__ W1,
    const float* __restrict__ b1,
    const float* __restrict__ W2,
    const float* __restrict__ b2,
    float* __restrict__ out)
{
    __shared__ unsigned long long tdup[4][64];
    const int lane = threadIdx.x & 31;
    const int w    = threadIdx.x >> 5;
    unsigned long long* td = tdup[w];

    unsigned long long w2[64];
#pragma unroll
    for (int k = 0; k < 64; k++)
        w2[k] = pack2(W2[k * 64 + lane], W2[k * 64 + lane + 32]);
    const unsigned long long b2p = pack2(b2[lane], b2[lane + 32]);

    // W1 rows 0..3, for channels lane and lane+32
    float wxa[4], wxb[4];
#pragma unroll
    for (int i = 0; i < 4; i++) {
        wxa[i] = W1[i * 64 + lane];
        wxb[i] = W1[i * 64 + lane + 32];
    }
    const float b1a = b1[lane], b1b = b1[lane + 32];

    const int gw = blockIdx.x * 4 + w;
    const int nW = gridDim.x * 4;

    for (int n = gw; n < NNODES; n += nW) {
        const float x0 = x[n * 4 + 0];
        const float x1 = x[n * 4 + 1];
        const float x2 = x[n * 4 + 2];
        const float x3 = x[n * 4 + 3];
        float t0 = fmaf(x3, wxa[3], fmaf(x2, wxa[2], fmaf(x1, wxa[1], fmaf(x0, wxa[0], b1a))));
        float t1 = fmaf(x3, wxb[3], fmaf(x2, wxb[2], fmaf(x1, wxb[1], fmaf(x0, wxb[0], b1b))));

        g_a[(size_t)n * 64 + lane]      = t0;
        g_a[(size_t)n * 64 + 32 + lane] = t1;

        // self-loop: rel = 0 -> t is exactly g_a[n]
        float r0 = fmaxf(t0, 0.0f), r1 = fmaxf(t1, 0.0f);
        td[lane]      = pack2(r0, r0);
        td[lane + 32] = pack2(r1, r1);
        __syncwarp();
        float h0, h1;
        gemm64(td, w2, b2p, h0, h1);
        __syncwarp();

        out[(size_t)n * 64 + lane]      = h0;
        out[(size_t)n * 64 + 32 + lane] = h1;
    }
}

// ---------------------------------------------------------------------------
// Kernel 2: per-edge. Each warp owns a contiguous chunk of the (dst-sorted)
// edge list; keeps a running per-dst max in registers; flushes with 2
// warp-wide atomicMaxF per dst segment. Skips src==dst (self-loops + pads).
// ---------------------------------------------------------------------------
__global__ void __launch_bounds__(128) edge_kernel(
    const int* __restrict__ ei, long long E,
    const float* __restrict__ pos,
    const float* __restrict__ W1,
    const float* __restrict__ W2,
    const float* __restrict__ b2,
    float* __restrict__ out)
{
    __shared__ unsigned long long tdup[4][64];
    const int lane = threadIdx.x & 31;
    const int w    = threadIdx.x >> 5;
    unsigned long long* td = tdup[w];

    unsigned long long w2[64];
#pragma unroll
    for (int k = 0; k < 64; k++)
        w2[k] = pack2(W2[k * 64 + lane], W2[k * 64 + lane + 32]);
    const unsigned long long b2p = pack2(b2[lane], b2[lane + 32]);

    // W1 rows 4..6 (rel terms), channels lane and lane+32
    const float wra0 = W1[4 * 64 + lane],      wra1 = W1[5 * 64 + lane],      wra2 = W1[6 * 64 + lane];
    const float wrb0 = W1[4 * 64 + lane + 32], wrb1 = W1[5 * 64 + lane + 32], wrb2 = W1[6 * 64 + lane + 32];

    const long long gw = blockIdx.x * 4 + w;
    const long long nW = (long long)gridDim.x * 4;
    const long long chunk = (E + nW - 1) / nW;
    const long long e0 = gw * chunk;
    long long e1 = e0 + chunk; if (e1 > E) e1 = E;

    const int* __restrict__ srcA = ei;
    const int* __restrict__ dstA = ei + E;

    int cur = -1;
    float m0 = -3.4e38f, m1 = -3.4e38f;

    for (long long e = e0; e < e1; ++e) {
        const int s = srcA[e];
        const int d = dstA[e];
        if (s == d) continue;                 // self-loops (handled in node_kernel) + pads

        if (d != cur) {
            if (cur >= 0) {
                atomicMaxF(&out[(size_t)cur * 64 + lane],      m0);
                atomicMaxF(&out[(size_t)cur * 64 + 32 + lane], m1);
            }
            cur = d;
            m0 = -3.4e38f; m1 = -3.4e38f;
        }

        const float r0 = pos[3 * s + 0] - pos[3 * d + 0];
        const float r1 = pos[3 * s + 1] - pos[3 * d + 1];
        const float r2 = pos[3 * s + 2] - pos[3 * d + 2];

        const float* __restrict__ ar = g_a + (size_t)s * 64;
        float t0 = ar[lane];
        float t1 = ar[lane + 32];
        t0 = fmaf(r2, wra2, fmaf(r1, wra1, fmaf(r0, wra0, t0)));
        t1 = fmaf(r2, wrb2, fmaf(r1, wrb1, fmaf(r0, wrb0, t1)));
        t0 = fmaxf(t0, 0.0f);
        t1 = fmaxf(t1, 0.0f);

        td[lane]      = pack2(t0, t0);
        td[lane + 32] = pack2(t1, t1);
        __syncwarp();
        float h0, h1;
        gemm64(td, w2, b2p, h0, h1);
        __syncwarp();

        m0 = fmaxf(m0, h0);
        m1 = fmaxf(m1, h1);
    }
    if (cur >= 0) {
        atomicMaxF(&out[(size_t)cur * 64 + lane],      m0);
        atomicMaxF(&out[(size_t)cur * 64 + 32 + lane], m1);
    }
}

// ---------------------------------------------------------------------------
// Kernel 3: copy pos and batch (as float) into the tail of the flattened
// tuple output, if the harness expects them.
// ---------------------------------------------------------------------------
__global__ void tail_kernel(const float* __restrict__ pos,
                            const int* __restrict__ batch,
                            float* __restrict__ out, int tail)
{
    int i = blockIdx.x * blockDim.x + threadIdx.x;
    if (i >= tail) return;
    float v;
    if (i < NNODES * 3) {
        v = pos[i];
    } else {
        int k = i - NNODES * 3;
        v = (k < NNODES) ? (float)batch[k] : 0.0f;
    }
    out[NNODES * 64 + i] = v;
}

extern "C" void kernel_launch(void* const* d_in, const int* in_sizes, int n_in,
                              void* d_out, int out_size) {
    const float* x     = (const float*)d_in[0];
    const float* pos   = (const float*)d_in[1];
    const int*   batch = (const int*)d_in[2];
    const int*   ei    = (const int*)d_in[3];
    const float* W1    = (const float*)d_in[4];
    const float* b1    = (const float*)d_in[5];
    const float* W2    = (const float*)d_in[6];
    const float* b2    = (const float*)d_in[7];
    float* out = (float*)d_out;

    const long long E = (long long)in_sizes[3] / 2;

    node_kernel<<<296, 128>>>(x, W1, b1, W2, b2, out);
    edge_kernel<<<444, 128>>>(ei, E, pos, W1, W2, b2, out);

    int tail = out_size - NNODES * 64;
    if (tail > 0) {
        tail_kernel<<<(tail + 255) / 256, 256>>>(pos, batch, out, tail);
    }
}

// round 2
// speedup vs baseline: 1.1663x; 1.1663x over previous
#include <cuda_runtime.h>
#include <cstdint>

#define NNODES 32768
#define EB 8   // edges per warp batch
#define NB 4   // nodes per warp batch

__device__ float g_a[NNODES * 64];   // pre-relu first-layer activations per node (b1 folded)

__device__ __forceinline__ void atomicMaxF(float* addr, float v) {
    if (v >= 0.0f) atomicMax((int*)addr, __float_as_int(v));
    else           atomicMin((unsigned int*)addr, __float_as_uint(v));
}

__device__ __forceinline__ unsigned long long pack2(float lo, float hi) {
    unsigned long long r;
    asm("mov.b64 %0, {%1,%2};" : "=l"(r) : "f"(lo), "f"(hi));
    return r;
}
__device__ __forceinline__ void unpack2(unsigned long long p, float& lo, float& hi) {
    asm("mov.b64 {%0,%1}, %2;" : "=f"(lo), "=f"(hi) : "l"(p));
}
__device__ __forceinline__ void fma2(unsigned long long& acc,
                                     unsigned long long a, unsigned long long b) {
    asm("fma.rn.f32x2 %0, %1, %2, %3;" : "=l"(acc) : "l"(a), "l"(b), "l"(acc));
}

// ---------------------------------------------------------------------------
// Kernel 1: per-node. g_a[n] = x[n]@W1[0:4] + b1 (pre-relu); out[n] init with
// self-loop contribution relu(g_a[n])@W2 + b2. Batched NB nodes per warp iter.
// ---------------------------------------------------------------------------
__global__ void __launch_bounds__(128, 2) node_kernel(
    const float* __restrict__ x,
    const float* __restrict__ W1,
    const float* __restrict__ b1,
    const float* __restrict__ W2,
    const float* __restrict__ b2,
    float* __restrict__ out)
{
    __shared__ unsigned long long tdup[4][NB][64];
    const int lane = threadIdx.x & 31;
    const int w    = threadIdx.x >> 5;

    unsigned long long w2[64];
#pragma unroll
    for (int k = 0; k < 64; k++)
        w2[k] = pack2(W2[k * 64 + lane], W2[k * 64 + lane + 32]);
    const unsigned long long b2p = pack2(b2[lane], b2[lane + 32]);

    float wxa[4], wxb[4];
#pragma unroll
    for (int i = 0; i < 4; i++) {
        wxa[i] = W1[i * 64 + lane];
        wxb[i] = W1[i * 64 + lane + 32];
    }
    const float b1a = b1[lane], b1b = b1[lane + 32];

    const int gw = blockIdx.x * 4 + w;
    const int nW = gridDim.x * 4;
    const int nodesPerWarp = (NNODES + nW - 1) / nW;
    const int n0 = gw * nodesPerWarp;
    int n1 = n0 + nodesPerWarp; if (n1 > NNODES) n1 = NNODES;

    for (int base = n0; base < n1; base += NB) {
        const int nb = min(NB, n1 - base);
        __syncwarp();
#pragma unroll
        for (int i = 0; i < NB; i++) {
            if (i >= nb) break;
            const int n = base + i;
            const float x0 = x[n * 4 + 0];
            const float x1 = x[n * 4 + 1];
            const float x2 = x[n * 4 + 2];
            const float x3 = x[n * 4 + 3];
            float t0 = fmaf(x3, wxa[3], fmaf(x2, wxa[2], fmaf(x1, wxa[1], fmaf(x0, wxa[0], b1a))));
            float t1 = fmaf(x3, wxb[3], fmaf(x2, wxb[2], fmaf(x1, wxb[1], fmaf(x0, wxb[0], b1b))));
            g_a[(size_t)n * 64 + lane]      = t0;
            g_a[(size_t)n * 64 + 32 + lane] = t1;
            t0 = fmaxf(t0, 0.0f);
            t1 = fmaxf(t1, 0.0f);
            tdup[w][i][lane]      = pack2(t0, t0);
            tdup[w][i][lane + 32] = pack2(t1, t1);
        }
        __syncwarp();

        unsigned long long acc[NB];
#pragma unroll
        for (int i = 0; i < NB; i++) acc[i] = b2p;
#pragma unroll
        for (int k = 0; k < 64; k += 2) {
#pragma unroll
            for (int i = 0; i < NB; i++) {
                ulonglong2 tp = *reinterpret_cast<const ulonglong2*>(&tdup[w][i][k]);
                fma2(acc[i], tp.x, w2[k]);
                fma2(acc[i], tp.y, w2[k + 1]);
            }
        }
#pragma unroll
        for (int i = 0; i < NB; i++) {
            if (i >= nb) break;
            float h0, h1;
            unpack2(acc[i], h0, h1);
            const int n = base + i;
            out[(size_t)n * 64 + lane]      = h0;
            out[(size_t)n * 64 + 32 + lane] = h1;
        }
    }
}

// ---------------------------------------------------------------------------
// Kernel 2: per-edge, batched EB per warp iteration. Running per-dst max in
// registers (dst-sorted edge list), flushed via atomicMaxF per segment.
// src==dst edges (self-loops + (0,0) pads) are skipped via a uniform mask.
// ---------------------------------------------------------------------------
__global__ void __launch_bounds__(128, 2) edge_kernel(
    const int* __restrict__ ei, long long E,
    const float* __restrict__ pos,
    const float* __restrict__ W1,
    const float* __restrict__ W2,
    const float* __restrict__ b2,
    float* __restrict__ out)
{
    __shared__ unsigned long long tdup[4][EB][64];
    const int lane = threadIdx.x & 31;
    const int w    = threadIdx.x >> 5;

    unsigned long long w2[64];
#pragma unroll
    for (int k = 0; k < 64; k++)
        w2[k] = pack2(W2[k * 64 + lane], W2[k * 64 + lane + 32]);
    const unsigned long long b2p = pack2(b2[lane], b2[lane + 32]);

    const float wra0 = W1[4 * 64 + lane],      wra1 = W1[5 * 64 + lane],      wra2 = W1[6 * 64 + lane];
    const float wrb0 = W1[4 * 64 + lane + 32], wrb1 = W1[5 * 64 + lane + 32], wrb2 = W1[6 * 64 + lane + 32];

    const long long gw = blockIdx.x * 4 + w;
    const long long nW = (long long)gridDim.x * 4;
    const long long chunk = (E + nW - 1) / nW;
    const long long e0 = gw * chunk;
    long long e1 = e0 + chunk; if (e1 > E) e1 = E;

    const int* __restrict__ srcA = ei;
    const int* __restrict__ dstA = ei + E;

    int cur = -1;
    float m0 = -3.4e38f, m1 = -3.4e38f;

    for (long long base = e0; base < e1; base += EB) {
        const int nb = (int)min((long long)EB, e1 - base);
        unsigned skipmask = 0;
        int dd[EB];

        __syncwarp();
#pragma unroll
        for (int i = 0; i < EB; i++) {
            if (i >= nb) { skipmask |= 1u << i; continue; }
            const int s = srcA[base + i];
            const int d = dstA[base + i];
            dd[i] = d;
            if (s == d) { skipmask |= 1u << i; continue; }

            const float r0 = pos[3 * s + 0] - pos[3 * d + 0];
            const float r1 = pos[3 * s + 1] - pos[3 * d + 1];
            const float r2 = pos[3 * s + 2] - pos[3 * d + 2];

            const float* __restrict__ ar = g_a + (size_t)s * 64;
            float t0 = ar[lane];
            float t1 = ar[lane + 32];
            t0 = fmaf(r2, wra2, fmaf(r1, wra1, fmaf(r0, wra0, t0)));
            t1 = fmaf(r2, wrb2, fmaf(r1, wrb1, fmaf(r0, wrb0, t1)));
            t0 = fmaxf(t0, 0.0f);
            t1 = fmaxf(t1, 0.0f);

            tdup[w][i][lane]      = pack2(t0, t0);
            tdup[w][i][lane + 32] = pack2(t1, t1);
        }
        __syncwarp();

        if (skipmask == (1u << EB) - 1u) continue;   // whole batch trivial (pad/self-loop region)

        // fused 8-edge gemm: 8 independent accumulator chains, w2 reused from regs
        unsigned long long acc[EB];
#pragma unroll
        for (int i = 0; i < EB; i++) acc[i] = b2p;
#pragma unroll
        for (int k = 0; k < 64; k += 2) {
#pragma unroll
            for (int i = 0; i < EB; i++) {
                ulonglong2 tp = *reinterpret_cast<const ulonglong2*>(&tdup[w][i][k]);
                fma2(acc[i], tp.x, w2[k]);
                fma2(acc[i], tp.y, w2[k + 1]);
            }
        }

#pragma unroll
        for (int i = 0; i < EB; i++) {
            if ((skipmask >> i) & 1u) continue;
            float h0, h1;
            unpack2(acc[i], h0, h1);
            const int d = dd[i];
            if (d != cur) {
                if (cur >= 0) {
                    atomicMaxF(&out[(size_t)cur * 64 + lane],      m0);
                    atomicMaxF(&out[(size_t)cur * 64 + 32 + lane], m1);
                }
                cur = d;
                m0 = -3.4e38f; m1 = -3.4e38f;
            }
            m0 = fmaxf(m0, h0);
            m1 = fmaxf(m1, h1);
        }
    }
    if (cur >= 0) {
        atomicMaxF(&out[(size_t)cur * 64 + lane],      m0);
        atomicMaxF(&out[(size_t)cur * 64 + 32 + lane], m1);
    }
}

// ---------------------------------------------------------------------------
// Kernel 3: pos + batch (as float) into the tail of the flattened tuple.
// ---------------------------------------------------------------------------
__global__ void tail_kernel(const float* __restrict__ pos,
                            const int* __restrict__ batch,
                            float* __restrict__ out, int tail)
{
    int i = blockIdx.x * blockDim.x + threadIdx.x;
    if (i >= tail) return;
    float v;
    if (i < NNODES * 3) {
        v = pos[i];
    } else {
        int k = i - NNODES * 3;
        v = (k < NNODES) ? (float)batch[k] : 0.0f;
    }
    out[NNODES * 64 + i] = v;
}

extern "C" void kernel_launch(void* const* d_in, const int* in_sizes, int n_in,
                              void* d_out, int out_size) {
    const float* x     = (const float*)d_in[0];
    const float* pos   = (const float*)d_in[1];
    const int*   batch = (const int*)d_in[2];
    const int*   ei    = (const int*)d_in[3];
    const float* W1    = (const float*)d_in[4];
    const float* b1    = (const float*)d_in[5];
    const float* W2    = (const float*)d_in[6];
    const float* b2    = (const float*)d_in[7];
    float* out = (float*)d_out;

    const long long E = (long long)in_sizes[3] / 2;

    node_kernel<<<296, 128>>>(x, W1, b1, W2, b2, out);
    edge_kernel<<<1184, 128>>>(ei, E, pos, W1, W2, b2, out);

    int tail = out_size - NNODES * 64;
    if (tail > 0) {
        tail_kernel<<<(tail + 255) / 256, 256>>>(pos, batch, out, tail);
    }
}

// round 3
// speedup vs baseline: 1.3127x; 1.1256x over previous
#include <cuda_runtime.h>
#include <cstdint>

#define NNODES 32768
#define EB 8   // edges/nodes per warp batch

__device__ float g_a[NNODES * 64];   // pre-relu first-layer activations (b1 folded)

__device__ __forceinline__ void atomicMaxF(float* addr, float v) {
    if (v >= 0.0f) atomicMax((int*)addr, __float_as_int(v));
    else           atomicMin((unsigned int*)addr, __float_as_uint(v));
}
__device__ __forceinline__ unsigned long long pack2(float lo, float hi) {
    unsigned long long r;
    asm("mov.b64 %0, {%1,%2};" : "=l"(r) : "f"(lo), "f"(hi));
    return r;
}
__device__ __forceinline__ void unpack2(unsigned long long p, float& lo, float& hi) {
    asm("mov.b64 {%0,%1}, %2;" : "=f"(lo), "=f"(hi) : "l"(p));
}
__device__ __forceinline__ void fma2(unsigned long long& acc,
                                     unsigned long long a, unsigned long long b) {
    asm("fma.rn.f32x2 %0, %1, %2, %3;" : "=l"(acc) : "l"(a), "l"(b), "l"(acc));
}

// Pack W2 into shared, k-pair-major:
//  w2a[q*32+j] = {W2[4q][j],   W2[4q+1][j],   W2[4q+2][j],   W2[4q+3][j]}      (channel j)
//  w2b[q*32+j] = same for channel j+32
__device__ __forceinline__ void stage_w2(const float* __restrict__ W2,
                                         float4* w2a, float4* w2b, int tid) {
    for (int idx = tid; idx < 16 * 32; idx += 256) {
        const int q = idx >> 5, j = idx & 31;
        const float* r0 = W2 + (4 * q) * 64;
        w2a[idx] = make_float4(r0[j],      r0[64 + j],      r0[128 + j],      r0[192 + j]);
        w2b[idx] = make_float4(r0[j + 32], r0[64 + j + 32], r0[128 + j + 32], r0[192 + j + 32]);
    }
}

// Fused EB-item 64x64 GEMV. td[i][k] = relu activations (plain f32).
// acc[i][0] accumulates channel `lane` (even-k in .lo, odd-k in .hi), acc[i][1] channel lane+32.
__device__ __forceinline__ void gemm_batch(const float* __restrict__ td,     // [EB][64]
                                           const float4* __restrict__ w2a,
                                           const float4* __restrict__ w2b,
                                           int lane,
                                           unsigned long long (&acc)[EB][2]) {
#pragma unroll
    for (int i = 0; i < EB; i++) { acc[i][0] = 0ull; acc[i][1] = 0ull; }
#pragma unroll
    for (int q = 0; q < 16; q++) {
        const ulonglong2 wa = *reinterpret_cast<const ulonglong2*>(&w2a[q * 32 + lane]);
        const ulonglong2 wb = *reinterpret_cast<const ulonglong2*>(&w2b[q * 32 + lane]);
#pragma unroll
        for (int i = 0; i < EB; i++) {
            const ulonglong2 tq = *reinterpret_cast<const ulonglong2*>(&td[i * 64 + q * 4]);
            fma2(acc[i][0], tq.x, wa.x);
            fma2(acc[i][0], tq.y, wa.y);
            fma2(acc[i][1], tq.x, wb.x);
            fma2(acc[i][1], tq.y, wb.y);
        }
    }
}

// ---------------------------------------------------------------------------
// Kernel 1: per-node. g_a[n] = x[n]@W1[0:4]+b1; out[n] = relu(g_a[n])@W2+b2
// (self-loop contribution, also initializes out).
// ---------------------------------------------------------------------------
__global__ void __launch_bounds__(256, 2) node_kernel(
    const float* __restrict__ x,
    const float* __restrict__ W1,
    const float* __restrict__ b1,
    const float* __restrict__ W2,
    const float* __restrict__ b2,
    float* __restrict__ out)
{
    __shared__ float4 w2a[16 * 32];
    __shared__ float4 w2b[16 * 32];
    __shared__ __align__(16) float tds[8][EB * 64];

    const int tid = threadIdx.x;
    const int lane = tid & 31;
    const int w = tid >> 5;
    stage_w2(W2, w2a, w2b, tid);
    __syncthreads();

    float* td = tds[w];

    float wxa[4], wxb[4];
#pragma unroll
    for (int i = 0; i < 4; i++) { wxa[i] = W1[i * 64 + lane]; wxb[i] = W1[i * 64 + lane + 32]; }
    const float b1a = b1[lane], b1b = b1[lane + 32];
    const float b2a = b2[lane], b2b = b2[lane + 32];

    const int gw = blockIdx.x * 8 + w;
    const int nW = gridDim.x * 8;
    const int perWarp = (NNODES + nW - 1) / nW;
    const int n0 = gw * perWarp;
    int n1 = n0 + perWarp; if (n1 > NNODES) n1 = NNODES;

    for (int base = n0; base < n1; base += EB) {
        const int nb = min(EB, n1 - base);
        __syncwarp();
#pragma unroll
        for (int i = 0; i < EB; i++) {
            if (i >= nb) break;
            const int n = base + i;
            const float x0 = x[n * 4 + 0], x1 = x[n * 4 + 1];
            const float x2 = x[n * 4 + 2], x3 = x[n * 4 + 3];
            float t0 = fmaf(x3, wxa[3], fmaf(x2, wxa[2], fmaf(x1, wxa[1], fmaf(x0, wxa[0], b1a))));
            float t1 = fmaf(x3, wxb[3], fmaf(x2, wxb[2], fmaf(x1, wxb[1], fmaf(x0, wxb[0], b1b))));
            g_a[(size_t)n * 64 + lane]      = t0;
            g_a[(size_t)n * 64 + 32 + lane] = t1;
            td[i * 64 + lane]      = fmaxf(t0, 0.0f);
            td[i * 64 + lane + 32] = fmaxf(t1, 0.0f);
        }
        __syncwarp();

        unsigned long long acc[EB][2];
        gemm_batch(td, w2a, w2b, lane, acc);

#pragma unroll
        for (int i = 0; i < EB; i++) {
            if (i >= nb) break;
            float a, b, c, d;
            unpack2(acc[i][0], a, b);
            unpack2(acc[i][1], c, d);
            const int n = base + i;
            out[(size_t)n * 64 + lane]      = a + b + b2a;
            out[(size_t)n * 64 + 32 + lane] = c + d + b2b;
        }
    }
}

// ---------------------------------------------------------------------------
// Kernel 2: per-edge (dst-sorted list). Running per-dst max in registers,
// flushed via atomicMaxF. Skips src==dst (self-loops handled in node_kernel,
// (0,0) pads are no-ops).
// ---------------------------------------------------------------------------
__global__ void __launch_bounds__(256, 2) edge_kernel(
    const int* __restrict__ ei, long long E,
    const float* __restrict__ pos,
    const float* __restrict__ W1,
    const float* __restrict__ W2,
    const float* __restrict__ b2,
    float* __restrict__ out)
{
    __shared__ float4 w2a[16 * 32];
    __shared__ float4 w2b[16 * 32];
    __shared__ __align__(16) float tds[8][EB * 64];

    const int tid = threadIdx.x;
    const int lane = tid & 31;
    const int w = tid >> 5;
    stage_w2(W2, w2a, w2b, tid);
    __syncthreads();

    float* td = tds[w];

    const float wra0 = W1[4 * 64 + lane],      wra1 = W1[5 * 64 + lane],      wra2 = W1[6 * 64 + lane];
    const float wrb0 = W1[4 * 64 + lane + 32], wrb1 = W1[5 * 64 + lane + 32], wrb2 = W1[6 * 64 + lane + 32];
    const float b2a = b2[lane], b2b = b2[lane + 32];

    const long long gw = blockIdx.x * 8 + w;
    const long long nW = (long long)gridDim.x * 8;
    const long long chunk = (E + nW - 1) / nW;
    const long long e0 = gw * chunk;
    long long e1 = e0 + chunk; if (e1 > E) e1 = E;

    const int* __restrict__ srcA = ei;
    const int* __restrict__ dstA = ei + E;

    int cur = -1;
    float m0 = -3.4e38f, m1 = -3.4e38f;

    for (long long base = e0; base < e1; base += EB) {
        const int nb = (int)min((long long)EB, e1 - base);
        unsigned skip = 0;
        int dd[EB];

        __syncwarp();
#pragma unroll
        for (int i = 0; i < EB; i++) {
            if (i >= nb) { skip |= 1u << i; continue; }
            const int s = srcA[base + i];
            const int d = dstA[base + i];
            dd[i] = d;
            if (s == d) { skip |= 1u << i; continue; }

            const float r0 = pos[3 * s + 0] - pos[3 * d + 0];
            const float r1 = pos[3 * s + 1] - pos[3 * d + 1];
            const float r2 = pos[3 * s + 2] - pos[3 * d + 2];

            const float* __restrict__ ar = g_a + (size_t)s * 64;
            float t0 = ar[lane];
            float t1 = ar[lane + 32];
            t0 = fmaf(r2, wra2, fmaf(r1, wra1, fmaf(r0, wra0, t0)));
            t1 = fmaf(r2, wrb2, fmaf(r1, wrb1, fmaf(r0, wrb0, t1)));
            td[i * 64 + lane]      = fmaxf(t0, 0.0f);
            td[i * 64 + lane + 32] = fmaxf(t1, 0.0f);
        }
        __syncwarp();

        if (skip == (1u << EB) - 1u) continue;   // whole batch trivial (pad/self-loop region)

        unsigned long long acc[EB][2];
        gemm_batch(td, w2a, w2b, lane, acc);

#pragma unroll
        for (int i = 0; i < EB; i++) {
            if ((skip >> i) & 1u) continue;
            float a, b, c, d2;
            unpack2(acc[i][0], a, b);
            unpack2(acc[i][1], c, d2);
            const float h0 = a + b + b2a;
            const float h1 = c + d2 + b2b;
            const int d = dd[i];
            if (d != cur) {
                if (cur >= 0) {
                    atomicMaxF(&out[(size_t)cur * 64 + lane],      m0);
                    atomicMaxF(&out[(size_t)cur * 64 + 32 + lane], m1);
                }
                cur = d;
                m0 = -3.4e38f; m1 = -3.4e38f;
            }
            m0 = fmaxf(m0, h0);
            m1 = fmaxf(m1, h1);
        }
    }
    if (cur >= 0) {
        atomicMaxF(&out[(size_t)cur * 64 + lane],      m0);
        atomicMaxF(&out[(size_t)cur * 64 + 32 + lane], m1);
    }
}

// ---------------------------------------------------------------------------
// Kernel 3: pos + batch (as float) into the tail of the flattened tuple.
// ---------------------------------------------------------------------------
__global__ void tail_kernel(const float* __restrict__ pos,
                            const int* __restrict__ batch,
                            float* __restrict__ out, int tail)
{
    int i = blockIdx.x * blockDim.x + threadIdx.x;
    if (i >= tail) return;
    float v;
    if (i < NNODES * 3) {
        v = pos[i];
    } else {
        int k = i - NNODES * 3;
        v = (k < NNODES) ? (float)batch[k] : 0.0f;
    }
    out[NNODES * 64 + i] = v;
}

extern "C" void kernel_launch(void* const* d_in, const int* in_sizes, int n_in,
                              void* d_out, int out_size) {
    const float* x     = (const float*)d_in[0];
    const float* pos   = (const float*)d_in[1];
    const int*   batch = (const int*)d_in[2];
    const int*   ei    = (const int*)d_in[3];
    const float* W1    = (const float*)d_in[4];
    const float* b1    = (const float*)d_in[5];
    const float* W2    = (const float*)d_in[6];
    const float* b2    = (const float*)d_in[7];
    float* out = (float*)d_out;

    const long long E = (long long)in_sizes[3] / 2;

    node_kernel<<<148, 256>>>(x, W1, b1, W2, b2, out);
    edge_kernel<<<296, 256>>>(ei, E, pos, W1, W2, b2, out);

    int tail = out_size - NNODES * 64;
    if (tail > 0) {
        tail_kernel<<<(tail + 255) / 256, 256>>>(pos, batch, out, tail);
    }
}